// round 17
// baseline (speedup 1.0000x reference)
#include <cuda_runtime.h>
#include <math.h>

#define HD 256      // hidden dim
#define BB 2        // batch
#define LL 512      // seq len (L1 == L2)
#define NHEAD 8
#define DHEAD 32
#define NSPLIT 4    // match channel splits (64 channels each)

// ---------------- scratch (device globals; no allocation) ----------------
__device__ float g_q [BB*LL*HD];                 // 1 MB
__device__ float g_k [BB*LL*HD];                 // 1 MB
__device__ float g_h1[BB*LL*HD];                 // 1 MB (includes +b1)
__device__ float g_h2[BB*LL*HD];                 // 1 MB
__device__ float g_logits[(size_t)BB*NHEAD*LL*LL]; // 16 MB logits
__device__ float g_part[(size_t)NSPLIT*BB*LL*LL];  // 8 MB match partials
__device__ float g_alpha[BB*LL];                 // sum_c (w/2) h1[b,i,c]  (atomic)
__device__ float g_beta [BB*LL];                 // sum_c (w/2) h2[b,j,c]  (atomic)

// ---------------- packed fp32x2 helpers (Blackwell) ----------------
typedef unsigned long long u64p;

__device__ __forceinline__ u64p f2_pack(float lo, float hi) {
    u64p r; asm("mov.b64 %0, {%1, %2};" : "=l"(r) : "f"(lo), "f"(hi)); return r;
}
__device__ __forceinline__ void f2_unpack(u64p p, float& lo, float& hi) {
    asm("mov.b64 {%0, %1}, %2;" : "=f"(lo), "=f"(hi) : "l"(p));
}
__device__ __forceinline__ u64p f2_fma(u64p a, u64p b, u64p c) {
    u64p d; asm("fma.rn.f32x2 %0, %1, %2, %3;" : "=l"(d) : "l"(a), "l"(b), "l"(c)); return d;
}
__device__ __forceinline__ u64p f2_add(u64p a, u64p b) {
    u64p d; asm("add.rn.f32x2 %0, %1, %2;" : "=l"(d) : "l"(a), "l"(b)); return d;
}
__device__ __forceinline__ u64p f2_abs(u64p x) {
    float lo, hi; f2_unpack(x, lo, hi);
    lo = fabsf(lo); hi = fabsf(hi);
    return f2_pack(lo, hi);
}

#define SMS 36   // smem row stride (floats): granule stride 9 (odd) -> conflict-free

// =========================================================================
// K1: projections (K-packed).  job z: 0=q 1=k 2=h1(+b1) 3=h2
// 64x64 tile, 256 threads, 4i x 4j/thread; f32x2 packed along K.
// jobs 2/3 additionally accumulate alpha/beta partials via atomicAdd.
// grid (4, 16, 4) = 256 blocks.
// =========================================================================
__global__ __launch_bounds__(256) void proj_kernel(
    const float* __restrict__ e1, const float* __restrict__ e2,
    const float* __restrict__ ipw, const float* __restrict__ ipb,
    const float* __restrict__ W1,  const float* __restrict__ b1,
    const float* __restrict__ W2)
{
    const int job = blockIdx.z;
    const float* A; const float* W; const float* bias; int ldw; float* C;
    if (job == 0)      { A = e1; W = ipw;           bias = ipb;      ldw = HD;   C = g_q;  }
    else if (job == 1) { A = e2; W = ipw + HD*HD;   bias = ipb + HD; ldw = HD;   C = g_k;  }
    else if (job == 2) { A = e1; W = W1;            bias = b1;       ldw = 2*HD; C = g_h1; }
    else               { A = e2; W = W1 + HD;       bias = nullptr;  ldw = 2*HD; C = g_h2; }

    const int i0 = blockIdx.y * 64;
    const int j0 = blockIdx.x * 64;

    __shared__ __align__(16) float sA[64][SMS];   // [i-row][k] 32 k used
    __shared__ __align__(16) float sW[64][SMS];   // [j-row][k]

    const int tid = threadIdx.x;
    const int ty = tid >> 4;       // rows i0 + ty*4 + u
    const int tx = tid & 15;       // cols j0 + tx + 16*v

    u64p acc[4][4] = {};   // [u][v], packed over k-parity

    for (int k0 = 0; k0 < HD; k0 += 32) {
        float4 va[2], vw[2];
        int row_[2], kq[2];
#pragma unroll
        for (int r = 0; r < 2; r++) {
            int pidx = tid + r * 256;
            row_[r] = pidx >> 3; kq[r] = (pidx & 7) << 2;
            va[r] = *(const float4*)&A[(size_t)(i0 + row_[r]) * HD  + k0 + kq[r]];
            vw[r] = *(const float4*)&W[(size_t)(j0 + row_[r]) * ldw + k0 + kq[r]];
        }
        __syncthreads();
#pragma unroll
        for (int r = 0; r < 2; r++) {
            *(float4*)&sA[row_[r]][kq[r]] = va[r];
            *(float4*)&sW[row_[r]][kq[r]] = vw[r];
        }
        __syncthreads();

#pragma unroll
        for (int kk4 = 0; kk4 < 32; kk4 += 4) {
            ulonglong2 a[4], w[4];
#pragma unroll
            for (int u = 0; u < 4; u++) a[u] = *(const ulonglong2*)&sA[ty*4 + u][kk4];
#pragma unroll
            for (int v = 0; v < 4; v++) w[v] = *(const ulonglong2*)&sW[tx + 16*v][kk4];
#pragma unroll
            for (int u = 0; u < 4; u++)
#pragma unroll
                for (int v = 0; v < 4; v++) {
                    acc[u][v] = f2_fma(a[u].x, w[v].x, acc[u][v]);
                    acc[u][v] = f2_fma(a[u].y, w[v].y, acc[u][v]);
                }
        }
        __syncthreads();
    }

    float bv[4] = {0.f, 0.f, 0.f, 0.f};
    if (bias) {
#pragma unroll
        for (int v = 0; v < 4; v++) bv[v] = bias[j0 + tx + 16*v];
    }

    float val[4][4];
#pragma unroll
    for (int u = 0; u < 4; u++) {
        const size_t rowoff = (size_t)(i0 + ty*4 + u) * HD + j0 + tx;
#pragma unroll
        for (int v = 0; v < 4; v++) {
            float lo, hi;
            f2_unpack(acc[u][v], lo, hi);
            val[u][v] = lo + hi + bv[v];
            C[rowoff + 16*v] = val[u][v];
        }
    }

    // ---- alpha/beta partials for h1/h2 jobs ----
    if (job >= 2) {
        float w2v[4];
#pragma unroll
        for (int v = 0; v < 4; v++) w2v[v] = 0.5f * W2[j0 + tx + 16*v];
        float* dst = (job == 2) ? g_alpha : g_beta;
#pragma unroll
        for (int u = 0; u < 4; u++) {
            float s = val[u][0]*w2v[0] + val[u][1]*w2v[1]
                    + val[u][2]*w2v[2] + val[u][3]*w2v[3];
#pragma unroll
            for (int o = 8; o; o >>= 1) s += __shfl_xor_sync(0xffffffffu, s, o);
            if (tx == 0) atomicAdd(&dst[i0 + ty*4 + u], s);
        }
    }
}

// =========================================================================
// K2 (FUSED): match partial tiles (z<8, 2-chunk, launched FIRST) +
//             logits tiles (z>=8, 1-chunk backfill).  (R16 verbatim)
// =========================================================================
__global__ __launch_bounds__(128) void mid_kernel(
    const float* __restrict__ W2, float* __restrict__ P)
{
    const int z  = blockIdx.z;
    const int i0 = blockIdx.y * 64;
    const int j0 = blockIdx.x * 64;

    __shared__ __align__(16) float sA[64][SMS];
    __shared__ __align__(16) float sB[64][SMS];
    __shared__ __align__(16) float sw[64];

    const int tid = threadIdx.x;
    const int ty = tid >> 4;
    const int tx = tid & 15;

    u64p acc[8][4] = {};

    if (z < NSPLIT*BB) {
        const int b  = z & 1;
        const int s  = z >> 1;
        const int c0 = s * 64;
        const float* Ag = g_h1 + (size_t)b * LL * HD + c0;
        const float* Bg = g_h2 + (size_t)b * LL * HD + c0;

        if (tid < 64) sw[tid] = 0.5f * W2[c0 + tid];

        for (int kc = 0; kc < 64; kc += 32) {
            float4 va[4], vb[4];
            int rr[4], kq[4];
#pragma unroll
            for (int r = 0; r < 4; r++) {
                int pidx = tid + r * 128;
                rr[r] = pidx >> 3; kq[r] = (pidx & 7) << 2;
                va[r] = *(const float4*)&Ag[(size_t)(i0 + rr[r]) * HD + kc + kq[r]];
                vb[r] = *(const float4*)&Bg[(size_t)(j0 + rr[r]) * HD + kc + kq[r]];
            }
            __syncthreads();
#pragma unroll
            for (int r = 0; r < 4; r++) {
                *(float4*)&sA[rr[r]][kq[r]] = va[r];
                *(float4*)&sB[rr[r]][kq[r]] = vb[r];
            }
            __syncthreads();

#pragma unroll
            for (int k4 = 0; k4 < 32; k4 += 4) {
                const u64p w01 = *(const u64p*)&sw[kc + k4];
                const u64p w23 = *(const u64p*)&sw[kc + k4 + 2];
                ulonglong2 bq[4];
#pragma unroll
                for (int v = 0; v < 4; v++)
                    bq[v] = *(const ulonglong2*)&sB[tx + 16*v][k4];
#pragma unroll
                for (int u = 0; u < 8; u++) {
                    const ulonglong2 aq = *(const ulonglong2*)&sA[ty*8 + u][k4];
#pragma unroll
                    for (int v = 0; v < 4; v++) {
                        acc[u][v] = f2_fma(f2_abs(f2_add(aq.x, bq[v].x)), w01, acc[u][v]);
                        acc[u][v] = f2_fma(f2_abs(f2_add(aq.y, bq[v].y)), w23, acc[u][v]);
                    }
                }
            }
        }
        float* Pd = P + (size_t)z * LL * LL;
#pragma unroll
        for (int u = 0; u < 8; u++) {
            const size_t ro = (size_t)(i0 + ty*8 + u) * LL + j0 + tx;
#pragma unroll
            for (int v = 0; v < 4; v++) {
                float lo, hi;
                f2_unpack(acc[u][v], lo, hi);
                Pd[ro + 16*v] = lo + hi;
            }
        }
    } else {
        const int zz = z - NSPLIT*BB;
        const int b = zz >> 3, h = zz & 7;
        const float* Ag = g_q + (size_t)b * LL * HD + h * DHEAD;
        const float* Bg = g_k + (size_t)b * LL * HD + h * DHEAD;

        {
            float4 va[4], vb[4];
            int rr[4], kq[4];
#pragma unroll
            for (int r = 0; r < 4; r++) {
                int pidx = tid + r * 128;
                rr[r] = pidx >> 3; kq[r] = (pidx & 7) << 2;
                va[r] = *(const float4*)&Ag[(size_t)(i0 + rr[r]) * HD + kq[r]];
                vb[r] = *(const float4*)&Bg[(size_t)(j0 + rr[r]) * HD + kq[r]];
            }
#pragma unroll
            for (int r = 0; r < 4; r++) {
                *(float4*)&sA[rr[r]][kq[r]] = va[r];
                *(float4*)&sB[rr[r]][kq[r]] = vb[r];
            }
        }
        __syncthreads();

#pragma unroll
        for (int k4 = 0; k4 < 32; k4 += 4) {
            ulonglong2 bq[4];
#pragma unroll
            for (int v = 0; v < 4; v++)
                bq[v] = *(const ulonglong2*)&sB[tx + 16*v][k4];
#pragma unroll
            for (int u = 0; u < 8; u++) {
                const ulonglong2 aq = *(const ulonglong2*)&sA[ty*8 + u][k4];
#pragma unroll
                for (int v = 0; v < 4; v++) {
                    acc[u][v] = f2_fma(aq.x, bq[v].x, acc[u][v]);
                    acc[u][v] = f2_fma(aq.y, bq[v].y, acc[u][v]);
                }
            }
        }
        const float scale = 0.1767766952966369f; // 1/sqrt(32)
        float* C = g_logits + (size_t)zz * LL * LL;
#pragma unroll
        for (int u = 0; u < 8; u++) {
            const size_t ro = (size_t)(i0 + ty*8 + u) * LL + j0 + tx;
#pragma unroll
            for (int v = 0; v < 4; v++) {
                float lo, hi;
                f2_unpack(acc[u][v], lo, hi);
                C[ro + 16*v] = (lo + hi) * scale;
            }
        }
    }
}

// =========================================================================
// K3 (FUSED TAIL): softmax+head-mean blocks (bid<1024) + combine (bid>=1024).
// softmax: one block per (b,i); warp h owns head h's row (LDG.128 loads).
// combine: out = sigmoid(alpha_i + beta_j + sum_s P_s + b2), 16 floats/thread.
// =========================================================================
__global__ __launch_bounds__(256) void tail_kernel(
    const float* __restrict__ P, const float* __restrict__ b2,
    float* __restrict__ out)
{
    const int bid = blockIdx.x;
    const int t = threadIdx.x;

    if (bid < BB*LL) {
        // ----------------------- softmax + mean -----------------------
        const int b = bid >> 9;
        const int i = bid & 511;
        const int wid  = t >> 5;
        const int lane = t & 31;

        __shared__ float p[8][512];

        const float* row = g_logits + ((size_t)(b*8 + wid) * LL + i) * LL;

        float4 v[4];
        float mx = -1e30f;
#pragma unroll
        for (int r = 0; r < 4; r++) {
            v[r] = *(const float4*)&row[lane*4 + 128*r];
            mx = fmaxf(mx, fmaxf(fmaxf(v[r].x, v[r].y), fmaxf(v[r].z, v[r].w)));
        }
#pragma unroll
        for (int o = 16; o; o >>= 1) mx = fmaxf(mx, __shfl_xor_sync(0xffffffffu, mx, o));

        float s = 0.0f;
#pragma unroll
        for (int r = 0; r < 4; r++) {
            v[r].x = __expf(v[r].x - mx); v[r].y = __expf(v[r].y - mx);
            v[r].z = __expf(v[r].z - mx); v[r].w = __expf(v[r].w - mx);
            s += v[r].x + v[r].y + v[r].z + v[r].w;
        }
#pragma unroll
        for (int o = 16; o; o >>= 1) s += __shfl_xor_sync(0xffffffffu, s, o);
        const float inv = 1.0f / s;

#pragma unroll
        for (int r = 0; r < 4; r++) {
            float4 pv = make_float4(v[r].x*inv, v[r].y*inv, v[r].z*inv, v[r].w*inv);
            *(float4*)&p[wid][lane*4 + 128*r] = pv;
        }

        __syncthreads();

        const size_t o = ((size_t)b * LL + i) * LL;
#pragma unroll
        for (int jj = 0; jj < 2; jj++) {
            int j = t + jj * 256;
            float a = 0.0f;
#pragma unroll
            for (int h = 0; h < 8; h++) a += p[h][j];
            out[o + j] = a * 0.125f;
        }
    } else {
        // ----------------------- combine -----------------------
        const int cid = bid - BB*LL;
        const size_t n  = (size_t)LL * LL;
        const size_t nn = (size_t)BB * LL * LL;
        const size_t base = ((size_t)cid * 256 + t) * 16;

        const int b = (int)(base >> 18);
        const int rem = (int)(base & 262143);
        const int i = rem >> 9;
        const int j = rem & 511;

        const float a0 = g_alpha[b*LL + i] + b2[0];

        float4 bt[4], acc[4];
#pragma unroll
        for (int f = 0; f < 4; f++) {
            bt[f] = *(const float4*)&g_beta[b*LL + j + 4*f];
            acc[f] = make_float4(a0 + bt[f].x, a0 + bt[f].y, a0 + bt[f].z, a0 + bt[f].w);
        }
#pragma unroll
        for (int s = 0; s < NSPLIT; s++) {
            const float* Pp = &P[((size_t)(s*2 + b)) * n + rem];
#pragma unroll
            for (int f = 0; f < 4; f++) {
                float4 ps = *(const float4*)&Pp[4*f];
                acc[f].x += ps.x; acc[f].y += ps.y; acc[f].z += ps.z; acc[f].w += ps.w;
            }
        }
#pragma unroll
        for (int f = 0; f < 4; f++) {
            float4 o4;
            o4.x = 1.0f / (1.0f + __expf(-acc[f].x));
            o4.y = 1.0f / (1.0f + __expf(-acc[f].y));
            o4.z = 1.0f / (1.0f + __expf(-acc[f].z));
            o4.w = 1.0f / (1.0f + __expf(-acc[f].w));
            *(float4*)&out[nn + base + 4*f] = o4;
        }
    }
}

// =========================================================================
extern "C" void kernel_launch(void* const* d_in, const int* in_sizes, int n_in,
                              void* d_out, int out_size)
{
    const float* e1  = (const float*)d_in[0];  // (B,L1,H)
    const float* e2  = (const float*)d_in[1];  // (B,L2,H)
    const float* ipw = (const float*)d_in[2];  // (3H,H)
    const float* ipb = (const float*)d_in[3];  // (3H,)
    const float* W1  = (const float*)d_in[4];  // (H,2H)
    const float* b1  = (const float*)d_in[5];  // (H,)
    const float* W2  = (const float*)d_in[6];  // (1,H)
    const float* b2  = (const float*)d_in[7];  // (1,)
    float* out = (float*)d_out;                // [attn (B,L1,L2)] ++ [match (B,L1,L2)]

    float *P, *al, *be;
    cudaGetSymbolAddress((void**)&P,  g_part);
    cudaGetSymbolAddress((void**)&al, g_alpha);
    cudaGetSymbolAddress((void**)&be, g_beta);

    cudaMemsetAsync(al, 0, BB*LL*sizeof(float));
    cudaMemsetAsync(be, 0, BB*LL*sizeof(float));
    proj_kernel <<<dim3(HD/64, (BB*LL)/64, 4), 256>>>(e1, e2, ipw, ipb, W1, b1, W2);
    mid_kernel  <<<dim3(LL/64, LL/64, NSPLIT*BB + 16), 128>>>(W2, P);
    tail_kernel <<<BB*LL + (BB*LL*LL)/(256*16), 256>>>(P, b2, out);
}